// round 5
// baseline (speedup 1.0000x reference)
#include <cuda_runtime.h>
#include <math.h>
#include <cstdint>
#include <mma.h>

using namespace nvcuda;

#define BB 4
#define CC 512
#define CQ 64
#define NN 4096

// Scratch (device globals; no runtime allocation allowed)
__device__ float g_Q[(size_t)BB * NN * CQ];   // [B][N][Cq]  (transposed Q)
__device__ float g_K[(size_t)BB * CQ * NN];   // [B][Cq][N]
__device__ float g_V[(size_t)BB * CC * NN];   // [B][C][N]
__device__ float g_P[(size_t)BB * NN * NN];   // [B][N][N]  exp(energy), unnormalized
__device__ float g_L[(size_t)BB * NN];        // [B][N] row sums of exp(energy)

__device__ __forceinline__ uint32_t smem_u32(const void* p) {
    uint32_t a;
    asm("{ .reg .u64 t; cvta.to.shared.u64 t, %1; cvt.u32.u64 %0, t; }"
        : "=r"(a) : "l"(p));
    return a;
}
#define CP_ASYNC16(dst_u32, src_ptr) \
    asm volatile("cp.async.cg.shared.global [%0], [%1], 16;" \
                 :: "r"(dst_u32), "l"(src_ptr) : "memory")
#define CP_COMMIT() asm volatile("cp.async.commit_group;" ::: "memory")
#define CP_WAIT(n)  asm volatile("cp.async.wait_group %0;" :: "n"(n) : "memory")

#define ASTRIDE 40
#define BSTRIDE 136
#define EPST 132

// ===========================================================================
// zero l
// ===========================================================================
__global__ void zero_l_kernel(float* __restrict__ l) {
    l[blockIdx.x * 256 + threadIdx.x] = 0.0f;
}

// ===========================================================================
// WMMA tf32 NN GEMM (V projection):  C[m][n] = sum_k A[m][k] * B[k][n]
// 128x128 tile, K-chunk 32, 256 threads, 2-stage cp.async.
// ===========================================================================
#define NN_STAGE_FLOATS (128 * ASTRIDE + 32 * BSTRIDE)   // 9472
#define SMEM_NN_BYTES   (2 * NN_STAGE_FLOATS * 4)        // 75776

__global__ void __launch_bounds__(256, 2)
wmma_nn_kernel(const float* __restrict__ A, const float* __restrict__ B,
               float* __restrict__ C, int Kdim, int lda, int ldb, int ldc,
               size_t strideA, size_t strideB, size_t strideC) {
    extern __shared__ float sm[];

    const int bz = blockIdx.z;
    const int m0 = blockIdx.y * 128;
    const int n0 = blockIdx.x * 128;
    const float* Ab = A + bz * strideA + (size_t)m0 * lda;
    const float* Bb = B + bz * strideB + n0;
    float* Cb = C + bz * strideC;

    const int tid = threadIdx.x;
    const int wid = tid >> 5;
    const int wm = wid >> 1;
    const int wn = wid & 1;

    wmma::fragment<wmma::accumulator, 16, 16, 8, float> acc[2][4];
    #pragma unroll
    for (int f = 0; f < 2; f++)
        #pragma unroll
        for (int g = 0; g < 4; g++)
            wmma::fill_fragment(acc[f][g], 0.0f);

    const uint32_t smb = smem_u32(sm);

    auto issue = [&](int k0, int s) {
        const uint32_t as_u = smb + (uint32_t)(s * NN_STAGE_FLOATS) * 4;
        const uint32_t bs_u = as_u + 128 * ASTRIDE * 4;
        #pragma unroll
        for (int k = 0; k < 4; k++) {
            int t = tid + k * 256;
            int row = t >> 3, seg = t & 7;
            CP_ASYNC16(as_u + (uint32_t)(row * ASTRIDE + seg * 4) * 4,
                       Ab + (size_t)row * lda + k0 + seg * 4);
        }
        #pragma unroll
        for (int k = 0; k < 4; k++) {
            int t = tid + k * 256;
            int row = t >> 5, seg = t & 31;
            CP_ASYNC16(bs_u + (uint32_t)(row * BSTRIDE + seg * 4) * 4,
                       Bb + (size_t)(k0 + row) * ldb + seg * 4);
        }
        CP_COMMIT();
    };

    issue(0, 0);

    const int nchunks = Kdim >> 5;
    for (int c = 0; c < nchunks; c++) {
        const int s = c & 1;
        if (c + 1 < nchunks) { issue((c + 1) << 5, s ^ 1); CP_WAIT(1); }
        else                 { CP_WAIT(0); }
        __syncthreads();

        const float* As = sm + s * NN_STAGE_FLOATS;
        const float* Bs = As + 128 * ASTRIDE;

        #pragma unroll
        for (int kk = 0; kk < 4; kk++) {
            wmma::fragment<wmma::matrix_a, 16, 16, 8, wmma::precision::tf32, wmma::row_major> af[2];
            wmma::fragment<wmma::matrix_b, 16, 16, 8, wmma::precision::tf32, wmma::row_major> bf[4];
            #pragma unroll
            for (int f = 0; f < 2; f++)
                wmma::load_matrix_sync(af[f], As + (wm * 32 + f * 16) * ASTRIDE + kk * 8, ASTRIDE);
            #pragma unroll
            for (int g = 0; g < 4; g++)
                wmma::load_matrix_sync(bf[g], Bs + kk * 8 * BSTRIDE + wn * 64 + g * 16, BSTRIDE);
            #pragma unroll
            for (int f = 0; f < 2; f++)
                #pragma unroll
                for (int g = 0; g < 4; g++)
                    wmma::mma_sync(acc[f][g], af[f], bf[g], acc[f][g]);
        }
        __syncthreads();
    }

    #pragma unroll
    for (int f = 0; f < 2; f++)
        #pragma unroll
        for (int g = 0; g < 4; g++)
            wmma::store_matrix_sync(
                Cb + (size_t)(m0 + wm * 32 + f * 16) * ldc + n0 + wn * 64 + g * 16,
                acc[f][g], ldc, wmma::mem_row_major);
}

// ===========================================================================
// Energy kernel with fused exp + row-sum epilogue:
//   P[i][j] = exp(sum_o Q[i][o] * K[o][j]);  l[i] += row partial sums
// 128x128 tile, 256 threads, Kdim = CQ = 64 (2 chunks, 2-stage).
// ===========================================================================
__global__ void __launch_bounds__(256, 2)
energy_kernel(const float* __restrict__ Q, const float* __restrict__ K,
              float* __restrict__ P, float* __restrict__ l) {
    extern __shared__ float sm[];

    const int b  = blockIdx.z;
    const int i0 = blockIdx.y * 128;
    const int j0b = blockIdx.x * 128;
    const float* Qb = Q + ((size_t)b * NN + i0) * CQ;
    const float* Kb = K + (size_t)b * CQ * NN + j0b;
    float* Pb = P + (size_t)b * NN * NN;

    const int tid = threadIdx.x;
    const int wid = tid >> 5;
    const int wm = wid >> 1;
    const int wn = wid & 1;

    wmma::fragment<wmma::accumulator, 16, 16, 8, float> acc[2][4];
    #pragma unroll
    for (int f = 0; f < 2; f++)
        #pragma unroll
        for (int g = 0; g < 4; g++)
            wmma::fill_fragment(acc[f][g], 0.0f);

    const uint32_t smb = smem_u32(sm);

    auto issue = [&](int k0, int s) {
        const uint32_t as_u = smb + (uint32_t)(s * NN_STAGE_FLOATS) * 4;
        const uint32_t bs_u = as_u + 128 * ASTRIDE * 4;
        #pragma unroll
        for (int k = 0; k < 4; k++) {
            int t = tid + k * 256;
            int row = t >> 3, seg = t & 7;
            CP_ASYNC16(as_u + (uint32_t)(row * ASTRIDE + seg * 4) * 4,
                       Qb + (size_t)row * CQ + k0 + seg * 4);
        }
        #pragma unroll
        for (int k = 0; k < 4; k++) {
            int t = tid + k * 256;
            int row = t >> 5, seg = t & 31;
            CP_ASYNC16(bs_u + (uint32_t)(row * BSTRIDE + seg * 4) * 4,
                       Kb + (size_t)(k0 + row) * NN + seg * 4);
        }
        CP_COMMIT();
    };

    issue(0, 0);
    #pragma unroll
    for (int c = 0; c < 2; c++) {
        if (c == 0) { issue(32, 1); CP_WAIT(1); }
        else        { CP_WAIT(0); }
        __syncthreads();

        const float* As = sm + c * NN_STAGE_FLOATS;
        const float* Bs = As + 128 * ASTRIDE;

        #pragma unroll
        for (int kk = 0; kk < 4; kk++) {
            wmma::fragment<wmma::matrix_a, 16, 16, 8, wmma::precision::tf32, wmma::row_major> af[2];
            wmma::fragment<wmma::matrix_b, 16, 16, 8, wmma::precision::tf32, wmma::row_major> bf[4];
            #pragma unroll
            for (int f = 0; f < 2; f++)
                wmma::load_matrix_sync(af[f], As + (wm * 32 + f * 16) * ASTRIDE + kk * 8, ASTRIDE);
            #pragma unroll
            for (int g = 0; g < 4; g++)
                wmma::load_matrix_sync(bf[g], Bs + kk * 8 * BSTRIDE + wn * 64 + g * 16, BSTRIDE);
            #pragma unroll
            for (int f = 0; f < 2; f++)
                #pragma unroll
                for (int g = 0; g < 4; g++)
                    wmma::mma_sync(acc[f][g], af[f], bf[g], acc[f][g]);
        }
        __syncthreads();
    }

    // exp in registers, stage to smem
    float* Ep = sm;
    #pragma unroll
    for (int f = 0; f < 2; f++)
        #pragma unroll
        for (int g = 0; g < 4; g++) {
            #pragma unroll
            for (int e = 0; e < acc[f][g].num_elements; e++)
                acc[f][g].x[e] = __expf(acc[f][g].x[e]);
            wmma::store_matrix_sync(Ep + (wm * 32 + f * 16) * EPST + wn * 64 + g * 16,
                                    acc[f][g], EPST, wmma::mem_row_major);
        }
    __syncthreads();

    // each pair of threads handles one row: sum 64 + write 64
    const int row  = tid >> 1;
    const int half = tid & 1;
    const float* rp = Ep + row * EPST + half * 64;
    float* gp = Pb + (size_t)(i0 + row) * NN + j0b + half * 64;
    float s = 0.0f;
    #pragma unroll
    for (int k = 0; k < 16; k++) {
        float4 v = *(const float4*)(rp + k * 4);
        s += (v.x + v.y) + (v.z + v.w);
        *(float4*)(gp + k * 4) = v;
    }
    float so = __shfl_xor_sync(0xffffffffu, s, 1);
    if (half == 0)
        atomicAdd(&l[(size_t)b * NN + i0 + row], s + so);
}

// ===========================================================================
// Out GEMM (tf32 NT) with fused normalize + gamma + residual:
//   out[b][c][i] = gamma * (sum_j V[b][c][j] * P[b][i][j]) / l[b][i] + x[b][c][i]
// Tile 256(c) x 128(i), K-chunk 32, 512 threads, 3-stage cp.async.
// ===========================================================================
#define OT_M 256
#define OT_N 128
#define OT_STAGE_FLOATS ((OT_M + OT_N) * ASTRIDE)        // 15360
#define SMEM_OUT_BYTES  (3 * OT_STAGE_FLOATS * 4)        // 184320

__global__ void __launch_bounds__(512, 1)
wmma_out_kernel(const float* __restrict__ V, const float* __restrict__ P,
                const float* __restrict__ x, const float* __restrict__ gamma,
                const float* __restrict__ l, float* __restrict__ out) {
    extern __shared__ float sm[];

    const int b  = blockIdx.z;
    const int c0 = blockIdx.x * OT_M;   // x = c-tiles: adjacent blocks share P rows
    const int i0 = blockIdx.y * OT_N;
    const float* Vb = V + ((size_t)b * CC + c0) * NN;
    const float* Pb = P + ((size_t)b * NN + i0) * NN;

    const int tid = threadIdx.x;
    const int wid = tid >> 5;
    const int wm = wid >> 1;   // 0..7 -> m offset wm*32
    const int wn = wid & 1;    // 0..1 -> n offset wn*64

    wmma::fragment<wmma::accumulator, 16, 16, 8, float> acc[2][4];
    #pragma unroll
    for (int f = 0; f < 2; f++)
        #pragma unroll
        for (int g = 0; g < 4; g++)
            wmma::fill_fragment(acc[f][g], 0.0f);

    const uint32_t smb = smem_u32(sm);

    auto issue = [&](int j0, int s) {
        const uint32_t as_u = smb + (uint32_t)(s * OT_STAGE_FLOATS) * 4;
        const uint32_t bs_u = as_u + OT_M * ASTRIDE * 4;
        #pragma unroll
        for (int k = 0; k < 4; k++) {          // A: 256 rows x 8 segs = 2048
            int t = tid + k * 512;
            int row = t >> 3, seg = t & 7;
            CP_ASYNC16(as_u + (uint32_t)(row * ASTRIDE + seg * 4) * 4,
                       Vb + (size_t)row * NN + j0 + seg * 4);
        }
        #pragma unroll
        for (int k = 0; k < 2; k++) {          // B: 128 rows x 8 segs = 1024
            int t = tid + k * 512;
            int row = t >> 3, seg = t & 7;
            CP_ASYNC16(bs_u + (uint32_t)(row * ASTRIDE + seg * 4) * 4,
                       Pb + (size_t)row * NN + j0 + seg * 4);
        }
        CP_COMMIT();
    };

    issue(0, 0);
    issue(32, 1);

    const int nchunks = NN >> 5;   // 128
    for (int c = 0; c < nchunks; c++) {
        if (c + 2 < nchunks) { issue((c + 2) << 5, (c + 2) % 3); CP_WAIT(2); }
        else if (c + 1 < nchunks) { CP_WAIT(1); }
        else { CP_WAIT(0); }
        __syncthreads();

        const float* As = sm + (c % 3) * OT_STAGE_FLOATS;
        const float* Bs = As + OT_M * ASTRIDE;

        #pragma unroll
        for (int kk = 0; kk < 4; kk++) {
            wmma::fragment<wmma::matrix_a, 16, 16, 8, wmma::precision::tf32, wmma::row_major> af[2];
            wmma::fragment<wmma::matrix_b, 16, 16, 8, wmma::precision::tf32, wmma::col_major> bf[4];
            #pragma unroll
            for (int f = 0; f < 2; f++)
                wmma::load_matrix_sync(af[f], As + (wm * 32 + f * 16) * ASTRIDE + kk * 8, ASTRIDE);
            #pragma unroll
            for (int g = 0; g < 4; g++)
                wmma::load_matrix_sync(bf[g], Bs + (wn * 64 + g * 16) * ASTRIDE + kk * 8, ASTRIDE);
            #pragma unroll
            for (int f = 0; f < 2; f++)
                #pragma unroll
                for (int g = 0; g < 4; g++)
                    wmma::mma_sync(acc[f][g], af[f], bf[g], acc[f][g]);
        }
        __syncthreads();
    }

    // Stage accumulators, load 1/l, fused epilogue
    float* Ep = sm;
    float* linv = sm + OT_M * EPST;   // 128 floats
    #pragma unroll
    for (int f = 0; f < 2; f++)
        #pragma unroll
        for (int g = 0; g < 4; g++)
            wmma::store_matrix_sync(Ep + (wm * 32 + f * 16) * EPST + wn * 64 + g * 16,
                                    acc[f][g], EPST, wmma::mem_row_major);
    if (tid < 128)
        linv[tid] = 1.0f / l[(size_t)b * NN + i0 + tid];
    __syncthreads();

    const float gm = gamma[0];
    #pragma unroll
    for (int t = tid; t < OT_M * 32; t += 512) {
        int r = t >> 5, sc = t & 31;
        float4 a = *(const float4*)(Ep + r * EPST + sc * 4);
        size_t gi = ((size_t)b * CC + c0 + r) * NN + i0 + sc * 4;
        float4 xv = *(const float4*)(x + gi);
        float4 o;
        o.x = gm * a.x * linv[sc * 4 + 0] + xv.x;
        o.y = gm * a.y * linv[sc * 4 + 1] + xv.y;
        o.z = gm * a.z * linv[sc * 4 + 2] + xv.z;
        o.w = gm * a.w * linv[sc * 4 + 3] + xv.w;
        *(float4*)(out + gi) = o;
    }
}

// ---------------------------------------------------------------------------
// Fused Q+K projection (FFMA; one pass over x):
//   blockIdx.y == 0: Q[b][n][o] = sum_c Wq[o][c] x[b][c][n]  (transposed store)
//   blockIdx.y == 1: K[b][o][n] = sum_c Wk[o][c] x[b][c][n]
// ---------------------------------------------------------------------------
__global__ void proj_qk_kernel(const float* __restrict__ Wq,
                               const float* __restrict__ Wk,
                               const float* __restrict__ X,
                               float* __restrict__ Q,
                               float* __restrict__ K) {
    __shared__ float As[64 * 17];
    __shared__ float Bs[16 * 64];

    const int b  = blockIdx.z;
    const int mt = blockIdx.y;
    const float* W = mt ? Wk : Wq;
    const float* Xb = X + (size_t)b * CC * NN;
    const int n0 = blockIdx.x * 64;
    const int tid = threadIdx.x;
    const int tx = tid & 15;
    const int ty = tid >> 4;

    float acc[4][4] = {};

    for (int k0 = 0; k0 < CC; k0 += 16) {
        {
            int lin = tid * 4;
            int m = lin >> 4, k = lin & 15;
            float4 v = *(const float4*)(W + (size_t)m * CC + k0 + k);
            As[m * 17 + k + 0] = v.x; As[m * 17 + k + 1] = v.y;
            As[m * 17 + k + 2] = v.z; As[m * 17 + k + 3] = v.w;
        }
        {
            int lin = tid * 4;
            int k = lin >> 6, n = lin & 63;
            *(float4*)(Bs + k * 64 + n) =
                *(const float4*)(Xb + (size_t)(k0 + k) * NN + n0 + n);
        }
        __syncthreads();
        #pragma unroll
        for (int kk = 0; kk < 16; kk++) {
            float a[4], bv[4];
            #pragma unroll
            for (int i = 0; i < 4; i++) a[i] = As[(ty * 4 + i) * 17 + kk];
            #pragma unroll
            for (int j = 0; j < 4; j++) bv[j] = Bs[kk * 64 + tx * 4 + j];
            #pragma unroll
            for (int i = 0; i < 4; i++)
                #pragma unroll
                for (int j = 0; j < 4; j++)
                    acc[i][j] += a[i] * bv[j];
        }
        __syncthreads();
    }

    if (mt == 0) {
        float* Qb = Q + (size_t)b * NN * CQ;
        #pragma unroll
        for (int i = 0; i < 4; i++)
            #pragma unroll
            for (int j = 0; j < 4; j++)
                Qb[(size_t)(n0 + tx * 4 + j) * CQ + (ty * 4 + i)] = acc[i][j];
    } else {
        float* Kb = K + (size_t)b * CQ * NN;
        #pragma unroll
        for (int i = 0; i < 4; i++)
            #pragma unroll
            for (int j = 0; j < 4; j++)
                Kb[(size_t)(ty * 4 + i) * NN + (n0 + tx * 4 + j)] = acc[i][j];
    }
}

// ---------------------------------------------------------------------------
extern "C" void kernel_launch(void* const* d_in, const int* in_sizes, int n_in,
                              void* d_out, int out_size) {
    const float* x     = (const float*)d_in[0];
    const float* Wq    = (const float*)d_in[1];
    const float* Wk    = (const float*)d_in[2];
    const float* Wv    = (const float*)d_in[3];
    const float* gamma = (const float*)d_in[4];
    float* out = (float*)d_out;

    float *Q, *K, *V, *P, *L;
    cudaGetSymbolAddress((void**)&Q, g_Q);
    cudaGetSymbolAddress((void**)&K, g_K);
    cudaGetSymbolAddress((void**)&V, g_V);
    cudaGetSymbolAddress((void**)&P, g_P);
    cudaGetSymbolAddress((void**)&L, g_L);

    cudaFuncSetAttribute(wmma_nn_kernel,
                         cudaFuncAttributeMaxDynamicSharedMemorySize, SMEM_NN_BYTES);
    cudaFuncSetAttribute(energy_kernel,
                         cudaFuncAttributeMaxDynamicSharedMemorySize, SMEM_NN_BYTES);
    cudaFuncSetAttribute(wmma_out_kernel,
                         cudaFuncAttributeMaxDynamicSharedMemorySize, SMEM_OUT_BYTES);

    // zero row sums
    zero_l_kernel<<<BB * NN / 256, 256>>>(L);

    // Q+K projections fused (one x read)
    proj_qk_kernel<<<dim3(NN / 64, 2, BB), 256>>>(Wq, Wk, x, Q, K);

    // V projection (WMMA tf32)
    wmma_nn_kernel<<<dim3(NN / 128, CC / 128, BB), 256, SMEM_NN_BYTES>>>(
        Wv, x, V, CC, CC, NN, NN,
        0, (size_t)CC * NN, (size_t)CC * NN);

    // Energy + exp + row sums (no separate softmax pass)
    energy_kernel<<<dim3(NN / 128, NN / 128, BB), 256, SMEM_NN_BYTES>>>(Q, K, P, L);

    // Output GEMM + fused normalize/gamma/residual
    wmma_out_kernel<<<dim3(CC / OT_M, NN / OT_N, BB), 512, SMEM_OUT_BYTES>>>(
        V, P, x, gamma, L, out);
}

// round 6
// speedup vs baseline: 1.2323x; 1.2323x over previous
#include <cuda_runtime.h>
#include <cuda_bf16.h>
#include <math.h>
#include <cstdint>
#include <mma.h>

using namespace nvcuda;

#define BB 4
#define CC 512
#define CQ 64
#define NN 4096

// Scratch (device globals; no runtime allocation allowed)
__device__ float g_Q[(size_t)BB * NN * CQ];           // [B][N][Cq]
__device__ float g_K[(size_t)BB * CQ * NN];           // [B][Cq][N]
__device__ __nv_bfloat16 g_V[(size_t)BB * CC * NN];   // [B][C][N] bf16
__device__ __nv_bfloat16 g_P[(size_t)BB * NN * NN];   // [B][N][N] bf16 exp(energy)
__device__ float g_L[(size_t)BB * NN];                // [B][N] row sums

__device__ __forceinline__ uint32_t smem_u32(const void* p) {
    uint32_t a;
    asm("{ .reg .u64 t; cvta.to.shared.u64 t, %1; cvt.u32.u64 %0, t; }"
        : "=r"(a) : "l"(p));
    return a;
}
#define CP_ASYNC16(dst_u32, src_ptr) \
    asm volatile("cp.async.cg.shared.global [%0], [%1], 16;" \
                 :: "r"(dst_u32), "l"(src_ptr) : "memory")
#define CP_COMMIT() asm volatile("cp.async.commit_group;" ::: "memory")
#define CP_WAIT(n)  asm volatile("cp.async.wait_group %0;" :: "n"(n) : "memory")

#define ASTRIDE 40
#define BSTRIDE 136
#define EPST 132

__global__ void zero_l_kernel(float* __restrict__ l) {
    l[blockIdx.x * 256 + threadIdx.x] = 0.0f;
}

// ===========================================================================
// V projection (tf32 MMA, bf16 output):  V[b][c][n] = sum_k Wv[c][k] x[b][k][n]
// 128x128 tile, K-chunk 32, 256 threads, 2-stage cp.async.
// ===========================================================================
#define NN_STAGE_FLOATS (128 * ASTRIDE + 32 * BSTRIDE)   // 9472
#define SMEM_NN_BYTES   (2 * NN_STAGE_FLOATS * 4)        // 75776

__global__ void __launch_bounds__(256, 2)
vproj_kernel(const float* __restrict__ Wv, const float* __restrict__ X,
             __nv_bfloat16* __restrict__ V) {
    extern __shared__ float sm[];

    const int b  = blockIdx.z;
    const int m0 = blockIdx.y * 128;
    const int n0 = blockIdx.x * 128;
    const float* Ab = Wv + (size_t)m0 * CC;
    const float* Bb = X + (size_t)b * CC * NN + n0;

    const int tid = threadIdx.x;
    const int wid = tid >> 5;
    const int wm = wid >> 1;
    const int wn = wid & 1;

    wmma::fragment<wmma::accumulator, 16, 16, 8, float> acc[2][4];
    #pragma unroll
    for (int f = 0; f < 2; f++)
        #pragma unroll
        for (int g = 0; g < 4; g++)
            wmma::fill_fragment(acc[f][g], 0.0f);

    const uint32_t smb = smem_u32(sm);

    auto issue = [&](int k0, int s) {
        const uint32_t as_u = smb + (uint32_t)(s * NN_STAGE_FLOATS) * 4;
        const uint32_t bs_u = as_u + 128 * ASTRIDE * 4;
        #pragma unroll
        for (int k = 0; k < 4; k++) {
            int t = tid + k * 256;
            int row = t >> 3, seg = t & 7;
            CP_ASYNC16(as_u + (uint32_t)(row * ASTRIDE + seg * 4) * 4,
                       Ab + (size_t)row * CC + k0 + seg * 4);
        }
        #pragma unroll
        for (int k = 0; k < 4; k++) {
            int t = tid + k * 256;
            int row = t >> 5, seg = t & 31;
            CP_ASYNC16(bs_u + (uint32_t)(row * BSTRIDE + seg * 4) * 4,
                       Bb + (size_t)(k0 + row) * NN + seg * 4);
        }
        CP_COMMIT();
    };

    issue(0, 0);

    const int nchunks = CC >> 5;
    for (int c = 0; c < nchunks; c++) {
        const int s = c & 1;
        if (c + 1 < nchunks) { issue((c + 1) << 5, s ^ 1); CP_WAIT(1); }
        else                 { CP_WAIT(0); }
        __syncthreads();

        const float* As = sm + s * NN_STAGE_FLOATS;
        const float* Bs = As + 128 * ASTRIDE;

        #pragma unroll
        for (int kk = 0; kk < 4; kk++) {
            wmma::fragment<wmma::matrix_a, 16, 16, 8, wmma::precision::tf32, wmma::row_major> af[2];
            wmma::fragment<wmma::matrix_b, 16, 16, 8, wmma::precision::tf32, wmma::row_major> bf[4];
            #pragma unroll
            for (int f = 0; f < 2; f++)
                wmma::load_matrix_sync(af[f], As + (wm * 32 + f * 16) * ASTRIDE + kk * 8, ASTRIDE);
            #pragma unroll
            for (int g = 0; g < 4; g++)
                wmma::load_matrix_sync(bf[g], Bs + kk * 8 * BSTRIDE + wn * 64 + g * 16, BSTRIDE);
            #pragma unroll
            for (int f = 0; f < 2; f++)
                #pragma unroll
                for (int g = 0; g < 4; g++)
                    wmma::mma_sync(acc[f][g], af[f], bf[g], acc[f][g]);
        }
        __syncthreads();
    }

    // Stage fp32, convert to bf16 on global write
    float* Ep = sm;
    #pragma unroll
    for (int f = 0; f < 2; f++)
        #pragma unroll
        for (int g = 0; g < 4; g++)
            wmma::store_matrix_sync(Ep + (wm * 32 + f * 16) * EPST + wn * 64 + g * 16,
                                    acc[f][g], EPST, wmma::mem_row_major);
    __syncthreads();

    __nv_bfloat16* Vb = V + ((size_t)b * CC + m0) * NN + n0;
    #pragma unroll
    for (int t = tid; t < 128 * 32; t += 256) {
        int r = t >> 5, sc = t & 31;
        float4 a = *(const float4*)(Ep + r * EPST + sc * 4);
        __nv_bfloat162* wp = (__nv_bfloat162*)(Vb + (size_t)r * NN + sc * 4);
        wp[0] = __float22bfloat162_rn(make_float2(a.x, a.y));
        wp[1] = __float22bfloat162_rn(make_float2(a.z, a.w));
    }
}

// ===========================================================================
// Energy (tf32 MMA) + exp + row sums, bf16 P output.
// 128x128 tile, 256 threads, K = CQ = 64 (2 chunks, 2-stage).
// ===========================================================================
__global__ void __launch_bounds__(256, 2)
energy_kernel(const float* __restrict__ Q, const float* __restrict__ K,
              __nv_bfloat16* __restrict__ P, float* __restrict__ l) {
    extern __shared__ float sm[];

    const int b  = blockIdx.z;
    const int i0 = blockIdx.y * 128;
    const int j0b = blockIdx.x * 128;
    const float* Qb = Q + ((size_t)b * NN + i0) * CQ;
    const float* Kb = K + (size_t)b * CQ * NN + j0b;

    const int tid = threadIdx.x;
    const int wid = tid >> 5;
    const int wm = wid >> 1;
    const int wn = wid & 1;

    wmma::fragment<wmma::accumulator, 16, 16, 8, float> acc[2][4];
    #pragma unroll
    for (int f = 0; f < 2; f++)
        #pragma unroll
        for (int g = 0; g < 4; g++)
            wmma::fill_fragment(acc[f][g], 0.0f);

    const uint32_t smb = smem_u32(sm);

    auto issue = [&](int k0, int s) {
        const uint32_t as_u = smb + (uint32_t)(s * NN_STAGE_FLOATS) * 4;
        const uint32_t bs_u = as_u + 128 * ASTRIDE * 4;
        #pragma unroll
        for (int k = 0; k < 4; k++) {
            int t = tid + k * 256;
            int row = t >> 3, seg = t & 7;
            CP_ASYNC16(as_u + (uint32_t)(row * ASTRIDE + seg * 4) * 4,
                       Qb + (size_t)row * CQ + k0 + seg * 4);
        }
        #pragma unroll
        for (int k = 0; k < 4; k++) {
            int t = tid + k * 256;
            int row = t >> 5, seg = t & 31;
            CP_ASYNC16(bs_u + (uint32_t)(row * BSTRIDE + seg * 4) * 4,
                       Kb + (size_t)(k0 + row) * NN + seg * 4);
        }
        CP_COMMIT();
    };

    issue(0, 0);
    #pragma unroll
    for (int c = 0; c < 2; c++) {
        if (c == 0) { issue(32, 1); CP_WAIT(1); }
        else        { CP_WAIT(0); }
        __syncthreads();

        const float* As = sm + c * NN_STAGE_FLOATS;
        const float* Bs = As + 128 * ASTRIDE;

        #pragma unroll
        for (int kk = 0; kk < 4; kk++) {
            wmma::fragment<wmma::matrix_a, 16, 16, 8, wmma::precision::tf32, wmma::row_major> af[2];
            wmma::fragment<wmma::matrix_b, 16, 16, 8, wmma::precision::tf32, wmma::row_major> bf[4];
            #pragma unroll
            for (int f = 0; f < 2; f++)
                wmma::load_matrix_sync(af[f], As + (wm * 32 + f * 16) * ASTRIDE + kk * 8, ASTRIDE);
            #pragma unroll
            for (int g = 0; g < 4; g++)
                wmma::load_matrix_sync(bf[g], Bs + kk * 8 * BSTRIDE + wn * 64 + g * 16, BSTRIDE);
            #pragma unroll
            for (int f = 0; f < 2; f++)
                #pragma unroll
                for (int g = 0; g < 4; g++)
                    wmma::mma_sync(acc[f][g], af[f], bf[g], acc[f][g]);
        }
        __syncthreads();
    }

    // exp in registers, stage fp32 to smem
    float* Ep = sm;
    #pragma unroll
    for (int f = 0; f < 2; f++)
        #pragma unroll
        for (int g = 0; g < 4; g++) {
            #pragma unroll
            for (int e = 0; e < acc[f][g].num_elements; e++)
                acc[f][g].x[e] = __expf(acc[f][g].x[e]);
            wmma::store_matrix_sync(Ep + (wm * 32 + f * 16) * EPST + wn * 64 + g * 16,
                                    acc[f][g], EPST, wmma::mem_row_major);
        }
    __syncthreads();

    // each pair of threads: one row -> sum 64 + write 64 (bf16)
    const int row  = tid >> 1;
    const int half = tid & 1;
    const float* rp = Ep + row * EPST + half * 64;
    __nv_bfloat16* gp = P + (size_t)b * NN * NN +
                        (size_t)(i0 + row) * NN + j0b + half * 64;
    float s = 0.0f;
    #pragma unroll
    for (int k = 0; k < 16; k++) {
        float4 v = *(const float4*)(rp + k * 4);
        s += (v.x + v.y) + (v.z + v.w);
        __nv_bfloat162* wp = (__nv_bfloat162*)(gp + k * 4);
        wp[0] = __float22bfloat162_rn(make_float2(v.x, v.y));
        wp[1] = __float22bfloat162_rn(make_float2(v.z, v.w));
    }
    float so = __shfl_xor_sync(0xffffffffu, s, 1);
    if (half == 0)
        atomicAdd(&l[(size_t)b * NN + i0 + row], s + so);
}

// ===========================================================================
// Out GEMM (bf16 m16n16k16, NT) + fused normalize/gamma/residual:
//   out[b][c][i] = gamma * (sum_j V[b][c][j] * P[b][i][j]) / l[b][i] + x[b][c][i]
// Tile 256(c) x 128(i), K-chunk 64, 256 threads (8 warps, 4x2, 64x64/warp),
// 3-stage cp.async.
// ===========================================================================
#define OT_M 256
#define OT_N 128
#define KC 64
#define HST 72   // bf16 smem row stride (halves)
#define OT_STAGE_HALVES ((OT_M + OT_N) * HST)            // 27648
#define SMEM_OUT_BYTES  (3 * OT_STAGE_HALVES * 2)        // 165888

__global__ void __launch_bounds__(256, 1)
wmma_out_kernel(const __nv_bfloat16* __restrict__ V,
                const __nv_bfloat16* __restrict__ P,
                const float* __restrict__ x, const float* __restrict__ gamma,
                const float* __restrict__ l, float* __restrict__ out) {
    extern __shared__ float smf[];
    __nv_bfloat16* smh = (__nv_bfloat16*)smf;

    const int b  = blockIdx.x;              // batch innermost? no: see launch
    const int c0 = blockIdx.z * OT_M;       // c-tiles outermost
    const int i0 = blockIdx.y * OT_N;
    const __nv_bfloat16* Vb = V + ((size_t)b * CC + c0) * NN;
    const __nv_bfloat16* Pb = P + ((size_t)b * NN + i0) * NN;

    const int tid = threadIdx.x;
    const int wid = tid >> 5;
    const int wm = wid >> 1;   // 0..3 -> m offset wm*64
    const int wn = wid & 1;    // 0..1 -> n offset wn*64

    wmma::fragment<wmma::accumulator, 16, 16, 16, float> acc[4][4];
    #pragma unroll
    for (int f = 0; f < 4; f++)
        #pragma unroll
        for (int g = 0; g < 4; g++)
            wmma::fill_fragment(acc[f][g], 0.0f);

    const uint32_t smb = smem_u32(smh);

    auto issue = [&](int j0, int s) {
        const uint32_t as_u = smb + (uint32_t)(s * OT_STAGE_HALVES) * 2;
        const uint32_t bs_u = as_u + OT_M * HST * 2;
        #pragma unroll
        for (int k = 0; k < 8; k++) {          // A: 256 rows x 8 segs (16B = 8 halves)
            int t = tid + k * 256;
            int row = t >> 3, seg = t & 7;
            CP_ASYNC16(as_u + (uint32_t)(row * HST + seg * 8) * 2,
                       Vb + (size_t)row * NN + j0 + seg * 8);
        }
        #pragma unroll
        for (int k = 0; k < 4; k++) {          // B: 128 rows x 8 segs
            int t = tid + k * 256;
            int row = t >> 3, seg = t & 7;
            CP_ASYNC16(bs_u + (uint32_t)(row * HST + seg * 8) * 2,
                       Pb + (size_t)row * NN + j0 + seg * 8);
        }
        CP_COMMIT();
    };

    issue(0, 0);
    issue(KC, 1);

    const int nchunks = NN / KC;   // 64
    for (int c = 0; c < nchunks; c++) {
        if (c + 2 < nchunks) { issue((c + 2) * KC, (c + 2) % 3); CP_WAIT(2); }
        else if (c + 1 < nchunks) { CP_WAIT(1); }
        else { CP_WAIT(0); }
        __syncthreads();

        const __nv_bfloat16* As = smh + (c % 3) * OT_STAGE_HALVES;
        const __nv_bfloat16* Bs = As + OT_M * HST;

        #pragma unroll
        for (int kk = 0; kk < KC / 16; kk++) {
            wmma::fragment<wmma::matrix_a, 16, 16, 16, __nv_bfloat16, wmma::row_major> af[4];
            wmma::fragment<wmma::matrix_b, 16, 16, 16, __nv_bfloat16, wmma::col_major> bf[4];
            #pragma unroll
            for (int f = 0; f < 4; f++)
                wmma::load_matrix_sync(af[f], As + (wm * 64 + f * 16) * HST + kk * 16, HST);
            #pragma unroll
            for (int g = 0; g < 4; g++)
                wmma::load_matrix_sync(bf[g], Bs + (wn * 64 + g * 16) * HST + kk * 16, HST);
            #pragma unroll
            for (int f = 0; f < 4; f++)
                #pragma unroll
                for (int g = 0; g < 4; g++)
                    wmma::mma_sync(acc[f][g], af[f], bf[g], acc[f][g]);
        }
        __syncthreads();
    }

    // Stage accumulators (alias smem as fp32), fused epilogue
    float* Ep = smf;
    float* linv = smf + OT_M * EPST;   // 128 floats (fits in 162KB)
    #pragma unroll
    for (int f = 0; f < 4; f++)
        #pragma unroll
        for (int g = 0; g < 4; g++)
            wmma::store_matrix_sync(Ep + (wm * 64 + f * 16) * EPST + wn * 64 + g * 16,
                                    acc[f][g], EPST, wmma::mem_row_major);
    if (tid < 128)
        linv[tid] = 1.0f / l[(size_t)b * NN + i0 + tid];
    __syncthreads();

    const float gm = gamma[0];
    #pragma unroll
    for (int t = tid; t < OT_M * 32; t += 256) {
        int r = t >> 5, sc = t & 31;
        float4 a = *(const float4*)(Ep + r * EPST + sc * 4);
        size_t gi = ((size_t)b * CC + c0 + r) * NN + i0 + sc * 4;
        float4 xv = *(const float4*)(x + gi);
        float4 o;
        o.x = gm * a.x * linv[sc * 4 + 0] + xv.x;
        o.y = gm * a.y * linv[sc * 4 + 1] + xv.y;
        o.z = gm * a.z * linv[sc * 4 + 2] + xv.z;
        o.w = gm * a.w * linv[sc * 4 + 3] + xv.w;
        *(float4*)(out + gi) = o;
    }
}

// ---------------------------------------------------------------------------
// Fused Q+K projection (FFMA)
// ---------------------------------------------------------------------------
__global__ void proj_qk_kernel(const float* __restrict__ Wq,
                               const float* __restrict__ Wk,
                               const float* __restrict__ X,
                               float* __restrict__ Q,
                               float* __restrict__ K) {
    __shared__ float As[64 * 17];
    __shared__ float Bs[16 * 64];

    const int b  = blockIdx.z;
    const int mt = blockIdx.y;
    const float* W = mt ? Wk : Wq;
    const float* Xb = X + (size_t)b * CC * NN;
    const int n0 = blockIdx.x * 64;
    const int tid = threadIdx.x;
    const int tx = tid & 15;
    const int ty = tid >> 4;

    float acc[4][4] = {};

    for (int k0 = 0; k0 < CC; k0 += 16) {
        {
            int lin = tid * 4;
            int m = lin >> 4, k = lin & 15;
            float4 v = *(const float4*)(W + (size_t)m * CC + k0 + k);
            As[m * 17 + k + 0] = v.x; As[m * 17 + k + 1] = v.y;
            As[m * 17 + k + 2] = v.z; As[m * 17 + k + 3] = v.w;
        }
        {
            int lin = tid * 4;
            int k = lin >> 6, n = lin & 63;
            *(float4*)(Bs + k * 64 + n) =
                *(const float4*)(Xb + (size_t)(k0 + k) * NN + n0 + n);
        }
        __syncthreads();
        #pragma unroll
        for (int kk = 0; kk < 16; kk++) {
            float a[4], bv[4];
            #pragma unroll
            for (int i = 0; i < 4; i++) a[i] = As[(ty * 4 + i) * 17 + kk];
            #pragma unroll
            for (int j = 0; j < 4; j++) bv[j] = Bs[kk * 64 + tx * 4 + j];
            #pragma unroll
            for (int i = 0; i < 4; i++)
                #pragma unroll
                for (int j = 0; j < 4; j++)
                    acc[i][j] += a[i] * bv[j];
        }
        __syncthreads();
    }

    if (mt == 0) {
        float* Qb = Q + (size_t)b * NN * CQ;
        #pragma unroll
        for (int i = 0; i < 4; i++)
            #pragma unroll
            for (int j = 0; j < 4; j++)
                Qb[(size_t)(n0 + tx * 4 + j) * CQ + (ty * 4 + i)] = acc[i][j];
    } else {
        float* Kb = K + (size_t)b * CQ * NN;
        #pragma unroll
        for (int i = 0; i < 4; i++)
            #pragma unroll
            for (int j = 0; j < 4; j++)
                Kb[(size_t)(ty * 4 + i) * NN + (n0 + tx * 4 + j)] = acc[i][j];
    }
}

// ---------------------------------------------------------------------------
extern "C" void kernel_launch(void* const* d_in, const int* in_sizes, int n_in,
                              void* d_out, int out_size) {
    const float* x     = (const float*)d_in[0];
    const float* Wq    = (const float*)d_in[1];
    const float* Wk    = (const float*)d_in[2];
    const float* Wv    = (const float*)d_in[3];
    const float* gamma = (const float*)d_in[4];
    float* out = (float*)d_out;

    float *Q, *K, *L;
    __nv_bfloat16 *V, *P;
    cudaGetSymbolAddress((void**)&Q, g_Q);
    cudaGetSymbolAddress((void**)&K, g_K);
    cudaGetSymbolAddress((void**)&V, g_V);
    cudaGetSymbolAddress((void**)&P, g_P);
    cudaGetSymbolAddress((void**)&L, g_L);

    cudaFuncSetAttribute(vproj_kernel,
                         cudaFuncAttributeMaxDynamicSharedMemorySize, SMEM_NN_BYTES);
    cudaFuncSetAttribute(energy_kernel,
                         cudaFuncAttributeMaxDynamicSharedMemorySize, SMEM_NN_BYTES);
    cudaFuncSetAttribute(wmma_out_kernel,
                         cudaFuncAttributeMaxDynamicSharedMemorySize, SMEM_OUT_BYTES);

    zero_l_kernel<<<BB * NN / 256, 256>>>(L);

    proj_qk_kernel<<<dim3(NN / 64, 2, BB), 256>>>(Wq, Wk, x, Q, K);

    vproj_kernel<<<dim3(NN / 128, CC / 128, BB), 256, SMEM_NN_BYTES>>>(Wv, x, V);

    energy_kernel<<<dim3(NN / 128, NN / 128, BB), 256, SMEM_NN_BYTES>>>(Q, K, P, L);

    // grid: x=batch, y=i-tiles, z=c-tiles -> blocks sharing P rows (same y,
    // different z) and V rows stay temporally close for L2 reuse
    wmma_out_kernel<<<dim3(BB, NN / OT_N, CC / OT_M), 256, SMEM_OUT_BYTES>>>(
        V, P, x, gamma, L, out);
}

// round 7
// speedup vs baseline: 2.2946x; 1.8621x over previous
#include <cuda_runtime.h>
#include <cuda_bf16.h>
#include <math.h>
#include <cstdint>
#include <mma.h>

using namespace nvcuda;

#define BB 4
#define CC 512
#define CQ 64
#define NN 4096

// Scratch (device globals; no runtime allocation allowed)
__device__ float g_Q[(size_t)BB * NN * CQ];           // [B][N][Cq]
__device__ float g_K[(size_t)BB * CQ * NN];           // [B][Cq][N]
__device__ __nv_bfloat16 g_V[(size_t)BB * CC * NN];   // [B][C][N] bf16
__device__ __nv_bfloat16 g_P[(size_t)BB * NN * NN];   // [B][N][N] bf16 exp(energy)
__device__ float g_L[(size_t)BB * NN];                // [B][N] row sums

__device__ __forceinline__ uint32_t smem_u32(const void* p) {
    uint32_t a;
    asm("{ .reg .u64 t; cvta.to.shared.u64 t, %1; cvt.u32.u64 %0, t; }"
        : "=r"(a) : "l"(p));
    return a;
}
#define CP_ASYNC16(dst_u32, src_ptr) \
    asm volatile("cp.async.cg.shared.global [%0], [%1], 16;" \
                 :: "r"(dst_u32), "l"(src_ptr) : "memory")
#define CP_COMMIT() asm volatile("cp.async.commit_group;" ::: "memory")
#define CP_WAIT(n)  asm volatile("cp.async.wait_group %0;" :: "n"(n) : "memory")

#define ASTRIDE 40
#define BSTRIDE 136
#define EPST 132

__global__ void zero_l_kernel(float* __restrict__ l) {
    l[blockIdx.x * 256 + threadIdx.x] = 0.0f;
}

// ===========================================================================
// V projection (tf32 MMA, bf16 output):  V[b][c][n] = sum_k Wv[c][k] x[b][k][n]
// 128x128 tile, K-chunk 32, 256 threads, 2-stage cp.async.
// ===========================================================================
#define NN_STAGE_FLOATS (128 * ASTRIDE + 32 * BSTRIDE)   // 9472
#define SMEM_NN_BYTES   (2 * NN_STAGE_FLOATS * 4)        // 75776

__global__ void __launch_bounds__(256, 2)
vproj_kernel(const float* __restrict__ Wv, const float* __restrict__ X,
             __nv_bfloat16* __restrict__ V) {
    extern __shared__ float sm[];

    const int b  = blockIdx.z;
    const int m0 = blockIdx.y * 128;
    const int n0 = blockIdx.x * 128;
    const float* Ab = Wv + (size_t)m0 * CC;
    const float* Bb = X + (size_t)b * CC * NN + n0;

    const int tid = threadIdx.x;
    const int wid = tid >> 5;
    const int wm = wid >> 1;
    const int wn = wid & 1;

    wmma::fragment<wmma::accumulator, 16, 16, 8, float> acc[2][4];
    #pragma unroll
    for (int f = 0; f < 2; f++)
        #pragma unroll
        for (int g = 0; g < 4; g++)
            wmma::fill_fragment(acc[f][g], 0.0f);

    const uint32_t smb = smem_u32(sm);

    auto issue = [&](int k0, int s) {
        const uint32_t as_u = smb + (uint32_t)(s * NN_STAGE_FLOATS) * 4;
        const uint32_t bs_u = as_u + 128 * ASTRIDE * 4;
        #pragma unroll
        for (int k = 0; k < 4; k++) {
            int t = tid + k * 256;
            int row = t >> 3, seg = t & 7;
            CP_ASYNC16(as_u + (uint32_t)(row * ASTRIDE + seg * 4) * 4,
                       Ab + (size_t)row * CC + k0 + seg * 4);
        }
        #pragma unroll
        for (int k = 0; k < 4; k++) {
            int t = tid + k * 256;
            int row = t >> 5, seg = t & 31;
            CP_ASYNC16(bs_u + (uint32_t)(row * BSTRIDE + seg * 4) * 4,
                       Bb + (size_t)(k0 + row) * NN + seg * 4);
        }
        CP_COMMIT();
    };

    issue(0, 0);

    const int nchunks = CC >> 5;
    for (int c = 0; c < nchunks; c++) {
        const int s = c & 1;
        if (c + 1 < nchunks) { issue((c + 1) << 5, s ^ 1); CP_WAIT(1); }
        else                 { CP_WAIT(0); }
        __syncthreads();

        const float* As = sm + s * NN_STAGE_FLOATS;
        const float* Bs = As + 128 * ASTRIDE;

        #pragma unroll
        for (int kk = 0; kk < 4; kk++) {
            wmma::fragment<wmma::matrix_a, 16, 16, 8, wmma::precision::tf32, wmma::row_major> af[2];
            wmma::fragment<wmma::matrix_b, 16, 16, 8, wmma::precision::tf32, wmma::row_major> bf[4];
            #pragma unroll
            for (int f = 0; f < 2; f++)
                wmma::load_matrix_sync(af[f], As + (wm * 32 + f * 16) * ASTRIDE + kk * 8, ASTRIDE);
            #pragma unroll
            for (int g = 0; g < 4; g++)
                wmma::load_matrix_sync(bf[g], Bs + kk * 8 * BSTRIDE + wn * 64 + g * 16, BSTRIDE);
            #pragma unroll
            for (int f = 0; f < 2; f++)
                #pragma unroll
                for (int g = 0; g < 4; g++)
                    wmma::mma_sync(acc[f][g], af[f], bf[g], acc[f][g]);
        }
        __syncthreads();
    }

    // Stage fp32, convert to bf16 on global write (coalesced: 8B/lane)
    float* Ep = sm;
    #pragma unroll
    for (int f = 0; f < 2; f++)
        #pragma unroll
        for (int g = 0; g < 4; g++)
            wmma::store_matrix_sync(Ep + (wm * 32 + f * 16) * EPST + wn * 64 + g * 16,
                                    acc[f][g], EPST, wmma::mem_row_major);
    __syncthreads();

    __nv_bfloat16* Vb = V + ((size_t)b * CC + m0) * NN + n0;
    #pragma unroll
    for (int t = tid; t < 128 * 32; t += 256) {
        int r = t >> 5, sc = t & 31;
        float4 a = *(const float4*)(Ep + r * EPST + sc * 4);
        __nv_bfloat162 w0 = __float22bfloat162_rn(make_float2(a.x, a.y));
        __nv_bfloat162 w1 = __float22bfloat162_rn(make_float2(a.z, a.w));
        uint2 u = make_uint2(*(uint32_t*)&w0, *(uint32_t*)&w1);
        *(uint2*)(Vb + (size_t)r * NN + sc * 4) = u;
    }
}

// ===========================================================================
// Energy (tf32 MMA) + exp + row sums, bf16 P output.
// 128x128 tile, 256 threads, K = CQ = 64 (2 chunks, 2-stage).
// Epilogue: warp-per-row coalesced bf16 stores + shfl row-sum reduction.
// ===========================================================================
__global__ void __launch_bounds__(256, 2)
energy_kernel(const float* __restrict__ Q, const float* __restrict__ K,
              __nv_bfloat16* __restrict__ P, float* __restrict__ l) {
    extern __shared__ float sm[];

    const int b  = blockIdx.z;
    const int i0 = blockIdx.y * 128;
    const int j0b = blockIdx.x * 128;
    const float* Qb = Q + ((size_t)b * NN + i0) * CQ;
    const float* Kb = K + (size_t)b * CQ * NN + j0b;

    const int tid = threadIdx.x;
    const int wid = tid >> 5;
    const int lane = tid & 31;
    const int wm = wid >> 1;
    const int wn = wid & 1;

    wmma::fragment<wmma::accumulator, 16, 16, 8, float> acc[2][4];
    #pragma unroll
    for (int f = 0; f < 2; f++)
        #pragma unroll
        for (int g = 0; g < 4; g++)
            wmma::fill_fragment(acc[f][g], 0.0f);

    const uint32_t smb = smem_u32(sm);

    auto issue = [&](int k0, int s) {
        const uint32_t as_u = smb + (uint32_t)(s * NN_STAGE_FLOATS) * 4;
        const uint32_t bs_u = as_u + 128 * ASTRIDE * 4;
        #pragma unroll
        for (int k = 0; k < 4; k++) {
            int t = tid + k * 256;
            int row = t >> 3, seg = t & 7;
            CP_ASYNC16(as_u + (uint32_t)(row * ASTRIDE + seg * 4) * 4,
                       Qb + (size_t)row * CQ + k0 + seg * 4);
        }
        #pragma unroll
        for (int k = 0; k < 4; k++) {
            int t = tid + k * 256;
            int row = t >> 5, seg = t & 31;
            CP_ASYNC16(bs_u + (uint32_t)(row * BSTRIDE + seg * 4) * 4,
                       Kb + (size_t)(k0 + row) * NN + seg * 4);
        }
        CP_COMMIT();
    };

    issue(0, 0);
    #pragma unroll
    for (int c = 0; c < 2; c++) {
        if (c == 0) { issue(32, 1); CP_WAIT(1); }
        else        { CP_WAIT(0); }
        __syncthreads();

        const float* As = sm + c * NN_STAGE_FLOATS;
        const float* Bs = As + 128 * ASTRIDE;

        #pragma unroll
        for (int kk = 0; kk < 4; kk++) {
            wmma::fragment<wmma::matrix_a, 16, 16, 8, wmma::precision::tf32, wmma::row_major> af[2];
            wmma::fragment<wmma::matrix_b, 16, 16, 8, wmma::precision::tf32, wmma::row_major> bf[4];
            #pragma unroll
            for (int f = 0; f < 2; f++)
                wmma::load_matrix_sync(af[f], As + (wm * 32 + f * 16) * ASTRIDE + kk * 8, ASTRIDE);
            #pragma unroll
            for (int g = 0; g < 4; g++)
                wmma::load_matrix_sync(bf[g], Bs + kk * 8 * BSTRIDE + wn * 64 + g * 16, BSTRIDE);
            #pragma unroll
            for (int f = 0; f < 2; f++)
                #pragma unroll
                for (int g = 0; g < 4; g++)
                    wmma::mma_sync(acc[f][g], af[f], bf[g], acc[f][g]);
        }
        __syncthreads();
    }

    // exp in registers, stage fp32 to smem
    float* Ep = sm;
    #pragma unroll
    for (int f = 0; f < 2; f++)
        #pragma unroll
        for (int g = 0; g < 4; g++) {
            #pragma unroll
            for (int e = 0; e < acc[f][g].num_elements; e++)
                acc[f][g].x[e] = __expf(acc[f][g].x[e]);
            wmma::store_matrix_sync(Ep + (wm * 32 + f * 16) * EPST + wn * 64 + g * 16,
                                    acc[f][g], EPST, wmma::mem_row_major);
        }
    __syncthreads();

    // Warp-per-row epilogue: lane ell covers cols [4*ell, 4*ell+4).
    // One 8B store per lane (256B contiguous per warp) + shfl row-sum.
    __nv_bfloat16* Pbase = P + (size_t)b * NN * NN + (size_t)i0 * NN + j0b;
    float* lb = l + (size_t)b * NN + i0;
    #pragma unroll
    for (int k = 0; k < 16; k++) {
        const int r = wid + k * 8;
        float4 v = *(const float4*)(Ep + r * EPST + lane * 4);
        __nv_bfloat162 w0 = __float22bfloat162_rn(make_float2(v.x, v.y));
        __nv_bfloat162 w1 = __float22bfloat162_rn(make_float2(v.z, v.w));
        uint2 u = make_uint2(*(uint32_t*)&w0, *(uint32_t*)&w1);
        *(uint2*)(Pbase + (size_t)r * NN + lane * 4) = u;

        float s = (v.x + v.y) + (v.z + v.w);
        #pragma unroll
        for (int o = 16; o > 0; o >>= 1)
            s += __shfl_xor_sync(0xffffffffu, s, o);
        if (lane == 0)
            atomicAdd(lb + r, s);
    }
}

// ===========================================================================
// Out GEMM (bf16 m16n16k16, NT) + fused normalize/gamma/residual:
//   out[b][c][i] = gamma * (sum_j V[b][c][j] * P[b][i][j]) / l[b][i] + x[b][c][i]
// Tile 256(c) x 128(i), K-chunk 64, 256 threads (8 warps, 4x2, 64x64/warp),
// 3-stage cp.async.
// ===========================================================================
#define OT_M 256
#define OT_N 128
#define KC 64
#define HST 72   // bf16 smem row stride (halves)
#define OT_STAGE_HALVES ((OT_M + OT_N) * HST)            // 27648
#define SMEM_OUT_BYTES  (3 * OT_STAGE_HALVES * 2)        // 165888

__global__ void __launch_bounds__(256, 1)
wmma_out_kernel(const __nv_bfloat16* __restrict__ V,
                const __nv_bfloat16* __restrict__ P,
                const float* __restrict__ x, const float* __restrict__ gamma,
                const float* __restrict__ l, float* __restrict__ out) {
    extern __shared__ float smf[];
    __nv_bfloat16* smh = (__nv_bfloat16*)smf;

    const int b  = blockIdx.x;
    const int c0 = blockIdx.z * OT_M;
    const int i0 = blockIdx.y * OT_N;
    const __nv_bfloat16* Vb = V + ((size_t)b * CC + c0) * NN;
    const __nv_bfloat16* Pb = P + ((size_t)b * NN + i0) * NN;

    const int tid = threadIdx.x;
    const int wid = tid >> 5;
    const int wm = wid >> 1;
    const int wn = wid & 1;

    wmma::fragment<wmma::accumulator, 16, 16, 16, float> acc[4][4];
    #pragma unroll
    for (int f = 0; f < 4; f++)
        #pragma unroll
        for (int g = 0; g < 4; g++)
            wmma::fill_fragment(acc[f][g], 0.0f);

    const uint32_t smb = smem_u32(smh);

    auto issue = [&](int j0, int s) {
        const uint32_t as_u = smb + (uint32_t)(s * OT_STAGE_HALVES) * 2;
        const uint32_t bs_u = as_u + OT_M * HST * 2;
        #pragma unroll
        for (int k = 0; k < 8; k++) {
            int t = tid + k * 256;
            int row = t >> 3, seg = t & 7;
            CP_ASYNC16(as_u + (uint32_t)(row * HST + seg * 8) * 2,
                       Vb + (size_t)row * NN + j0 + seg * 8);
        }
        #pragma unroll
        for (int k = 0; k < 4; k++) {
            int t = tid + k * 256;
            int row = t >> 3, seg = t & 7;
            CP_ASYNC16(bs_u + (uint32_t)(row * HST + seg * 8) * 2,
                       Pb + (size_t)row * NN + j0 + seg * 8);
        }
        CP_COMMIT();
    };

    issue(0, 0);
    issue(KC, 1);

    const int nchunks = NN / KC;   // 64
    for (int c = 0; c < nchunks; c++) {
        if (c + 2 < nchunks) { issue((c + 2) * KC, (c + 2) % 3); CP_WAIT(2); }
        else if (c + 1 < nchunks) { CP_WAIT(1); }
        else { CP_WAIT(0); }
        __syncthreads();

        const __nv_bfloat16* As = smh + (c % 3) * OT_STAGE_HALVES;
        const __nv_bfloat16* Bs = As + OT_M * HST;

        #pragma unroll
        for (int kk = 0; kk < KC / 16; kk++) {
            wmma::fragment<wmma::matrix_a, 16, 16, 16, __nv_bfloat16, wmma::row_major> af[4];
            wmma::fragment<wmma::matrix_b, 16, 16, 16, __nv_bfloat16, wmma::col_major> bf[4];
            #pragma unroll
            for (int f = 0; f < 4; f++)
                wmma::load_matrix_sync(af[f], As + (wm * 64 + f * 16) * HST + kk * 16, HST);
            #pragma unroll
            for (int g = 0; g < 4; g++)
                wmma::load_matrix_sync(bf[g], Bs + (wn * 64 + g * 16) * HST + kk * 16, HST);
            #pragma unroll
            for (int f = 0; f < 4; f++)
                #pragma unroll
                for (int g = 0; g < 4; g++)
                    wmma::mma_sync(acc[f][g], af[f], bf[g], acc[f][g]);
        }
        __syncthreads();
    }

    // Stage accumulators (alias smem as fp32), fused epilogue
    float* Ep = smf;
    float* linv = smf + OT_M * EPST;
    #pragma unroll
    for (int f = 0; f < 4; f++)
        #pragma unroll
        for (int g = 0; g < 4; g++)
            wmma::store_matrix_sync(Ep + (wm * 64 + f * 16) * EPST + wn * 64 + g * 16,
                                    acc[f][g], EPST, wmma::mem_row_major);
    if (tid < 128)
        linv[tid] = 1.0f / l[(size_t)b * NN + i0 + tid];
    __syncthreads();

    const float gm = gamma[0];
    #pragma unroll
    for (int t = tid; t < OT_M * 32; t += 256) {
        int r = t >> 5, sc = t & 31;
        float4 a = *(const float4*)(Ep + r * EPST + sc * 4);
        size_t gi = ((size_t)b * CC + c0 + r) * NN + i0 + sc * 4;
        float4 xv = *(const float4*)(x + gi);
        float4 o;
        o.x = gm * a.x * linv[sc * 4 + 0] + xv.x;
        o.y = gm * a.y * linv[sc * 4 + 1] + xv.y;
        o.z = gm * a.z * linv[sc * 4 + 2] + xv.z;
        o.w = gm * a.w * linv[sc * 4 + 3] + xv.w;
        *(float4*)(out + gi) = o;
    }
}

// ---------------------------------------------------------------------------
// Fused Q+K projection (FFMA)
// ---------------------------------------------------------------------------
__global__ void proj_qk_kernel(const float* __restrict__ Wq,
                               const float* __restrict__ Wk,
                               const float* __restrict__ X,
                               float* __restrict__ Q,
                               float* __restrict__ K) {
    __shared__ float As[64 * 17];
    __shared__ float Bs[16 * 64];

    const int b  = blockIdx.z;
    const int mt = blockIdx.y;
    const float* W = mt ? Wk : Wq;
    const float* Xb = X + (size_t)b * CC * NN;
    const int n0 = blockIdx.x * 64;
    const int tid = threadIdx.x;
    const int tx = tid & 15;
    const int ty = tid >> 4;

    float acc[4][4] = {};

    for (int k0 = 0; k0 < CC; k0 += 16) {
        {
            int lin = tid * 4;
            int m = lin >> 4, k = lin & 15;
            float4 v = *(const float4*)(W + (size_t)m * CC + k0 + k);
            As[m * 17 + k + 0] = v.x; As[m * 17 + k + 1] = v.y;
            As[m * 17 + k + 2] = v.z; As[m * 17 + k + 3] = v.w;
        }
        {
            int lin = tid * 4;
            int k = lin >> 6, n = lin & 63;
            *(float4*)(Bs + k * 64 + n) =
                *(const float4*)(Xb + (size_t)(k0 + k) * NN + n0 + n);
        }
        __syncthreads();
        #pragma unroll
        for (int kk = 0; kk < 16; kk++) {
            float a[4], bv[4];
            #pragma unroll
            for (int i = 0; i < 4; i++) a[i] = As[(ty * 4 + i) * 17 + kk];
            #pragma unroll
            for (int j = 0; j < 4; j++) bv[j] = Bs[kk * 64 + tx * 4 + j];
            #pragma unroll
            for (int i = 0; i < 4; i++)
                #pragma unroll
                for (int j = 0; j < 4; j++)
                    acc[i][j] += a[i] * bv[j];
        }
        __syncthreads();
    }

    if (mt == 0) {
        float* Qb = Q + (size_t)b * NN * CQ;
        #pragma unroll
        for (int i = 0; i < 4; i++)
            #pragma unroll
            for (int j = 0; j < 4; j++)
                Qb[(size_t)(n0 + tx * 4 + j) * CQ + (ty * 4 + i)] = acc[i][j];
    } else {
        float* Kb = K + (size_t)b * CQ * NN;
        #pragma unroll
        for (int i = 0; i < 4; i++)
            #pragma unroll
            for (int j = 0; j < 4; j++)
                Kb[(size_t)(ty * 4 + i) * NN + (n0 + tx * 4 + j)] = acc[i][j];
    }
}

// ---------------------------------------------------------------------------
extern "C" void kernel_launch(void* const* d_in, const int* in_sizes, int n_in,
                              void* d_out, int out_size) {
    const float* x     = (const float*)d_in[0];
    const float* Wq    = (const float*)d_in[1];
    const float* Wk    = (const float*)d_in[2];
    const float* Wv    = (const float*)d_in[3];
    const float* gamma = (const float*)d_in[4];
    float* out = (float*)d_out;

    float *Q, *K, *L;
    __nv_bfloat16 *V, *P;
    cudaGetSymbolAddress((void**)&Q, g_Q);
    cudaGetSymbolAddress((void**)&K, g_K);
    cudaGetSymbolAddress((void**)&V, g_V);
    cudaGetSymbolAddress((void**)&P, g_P);
    cudaGetSymbolAddress((void**)&L, g_L);

    cudaFuncSetAttribute(vproj_kernel,
                         cudaFuncAttributeMaxDynamicSharedMemorySize, SMEM_NN_BYTES);
    cudaFuncSetAttribute(energy_kernel,
                         cudaFuncAttributeMaxDynamicSharedMemorySize, SMEM_NN_BYTES);
    cudaFuncSetAttribute(wmma_out_kernel,
                         cudaFuncAttributeMaxDynamicSharedMemorySize, SMEM_OUT_BYTES);

    zero_l_kernel<<<BB * NN / 256, 256>>>(L);

    proj_qk_kernel<<<dim3(NN / 64, 2, BB), 256>>>(Wq, Wk, x, Q, K);

    vproj_kernel<<<dim3(NN / 128, CC / 128, BB), 256, SMEM_NN_BYTES>>>(Wv, x, V);

    energy_kernel<<<dim3(NN / 128, NN / 128, BB), 256, SMEM_NN_BYTES>>>(Q, K, P, L);

    wmma_out_kernel<<<dim3(BB, NN / OT_N, CC / OT_M), 256, SMEM_OUT_BYTES>>>(
        V, P, x, gamma, L, out);
}

// round 8
// speedup vs baseline: 2.4324x; 1.0601x over previous
#include <cuda_runtime.h>
#include <cuda_bf16.h>
#include <math.h>
#include <cstdint>
#include <mma.h>

using namespace nvcuda;

#define BB 4
#define CC 512
#define CQ 64
#define NN 4096

// Scratch (device globals; no runtime allocation allowed)
__device__ float g_Q[(size_t)BB * NN * CQ];           // [B][N][Cq]
__device__ float g_K[(size_t)BB * CQ * NN];           // [B][Cq][N]
__device__ __nv_bfloat16 g_V[(size_t)BB * CC * NN];   // [B][C][N] bf16
__device__ __nv_bfloat16 g_P[(size_t)BB * NN * NN];   // [B][N][N] bf16 exp(energy)
__device__ float g_L[(size_t)BB * NN];                // [B][N] row sums

__device__ __forceinline__ uint32_t smem_u32(const void* p) {
    uint32_t a;
    asm("{ .reg .u64 t; cvta.to.shared.u64 t, %1; cvt.u32.u64 %0, t; }"
        : "=r"(a) : "l"(p));
    return a;
}
#define CP_ASYNC16(dst_u32, src_ptr) \
    asm volatile("cp.async.cg.shared.global [%0], [%1], 16;" \
                 :: "r"(dst_u32), "l"(src_ptr) : "memory")
#define CP_COMMIT() asm volatile("cp.async.commit_group;" ::: "memory")
#define CP_WAIT(n)  asm volatile("cp.async.wait_group %0;" :: "n"(n) : "memory")

#define ASTRIDE 40
#define BSTRIDE 136
#define EPST 132

__global__ void zero_l_kernel(float* __restrict__ l) {
    l[blockIdx.x * 256 + threadIdx.x] = 0.0f;
}

#define NN_STAGE_FLOATS (128 * ASTRIDE + 32 * BSTRIDE)   // 9472
#define SMEM_NN_BYTES   (2 * NN_STAGE_FLOATS * 4)        // 75776

// ===========================================================================
// V projection (tf32 MMA, bf16 output):  V[b][c][n] = sum_k Wv[c][k] x[b][k][n]
// ===========================================================================
__global__ void __launch_bounds__(256, 2)
vproj_kernel(const float* __restrict__ Wv, const float* __restrict__ X,
             __nv_bfloat16* __restrict__ V) {
    extern __shared__ float sm[];

    const int b  = blockIdx.z;
    const int m0 = blockIdx.y * 128;
    const int n0 = blockIdx.x * 128;
    const float* Ab = Wv + (size_t)m0 * CC;
    const float* Bb = X + (size_t)b * CC * NN + n0;

    const int tid = threadIdx.x;
    const int wid = tid >> 5;
    const int wm = wid >> 1;
    const int wn = wid & 1;

    wmma::fragment<wmma::accumulator, 16, 16, 8, float> acc[2][4];
    #pragma unroll
    for (int f = 0; f < 2; f++)
        #pragma unroll
        for (int g = 0; g < 4; g++)
            wmma::fill_fragment(acc[f][g], 0.0f);

    const uint32_t smb = smem_u32(sm);

    auto issue = [&](int k0, int s) {
        const uint32_t as_u = smb + (uint32_t)(s * NN_STAGE_FLOATS) * 4;
        const uint32_t bs_u = as_u + 128 * ASTRIDE * 4;
        #pragma unroll
        for (int k = 0; k < 4; k++) {
            int t = tid + k * 256;
            int row = t >> 3, seg = t & 7;
            CP_ASYNC16(as_u + (uint32_t)(row * ASTRIDE + seg * 4) * 4,
                       Ab + (size_t)row * CC + k0 + seg * 4);
        }
        #pragma unroll
        for (int k = 0; k < 4; k++) {
            int t = tid + k * 256;
            int row = t >> 5, seg = t & 31;
            CP_ASYNC16(bs_u + (uint32_t)(row * BSTRIDE + seg * 4) * 4,
                       Bb + (size_t)(k0 + row) * NN + seg * 4);
        }
        CP_COMMIT();
    };

    issue(0, 0);

    const int nchunks = CC >> 5;
    for (int c = 0; c < nchunks; c++) {
        const int s = c & 1;
        if (c + 1 < nchunks) { issue((c + 1) << 5, s ^ 1); CP_WAIT(1); }
        else                 { CP_WAIT(0); }
        __syncthreads();

        const float* As = sm + s * NN_STAGE_FLOATS;
        const float* Bs = As + 128 * ASTRIDE;

        #pragma unroll
        for (int kk = 0; kk < 4; kk++) {
            wmma::fragment<wmma::matrix_a, 16, 16, 8, wmma::precision::tf32, wmma::row_major> af[2];
            wmma::fragment<wmma::matrix_b, 16, 16, 8, wmma::precision::tf32, wmma::row_major> bf[4];
            #pragma unroll
            for (int f = 0; f < 2; f++)
                wmma::load_matrix_sync(af[f], As + (wm * 32 + f * 16) * ASTRIDE + kk * 8, ASTRIDE);
            #pragma unroll
            for (int g = 0; g < 4; g++)
                wmma::load_matrix_sync(bf[g], Bs + kk * 8 * BSTRIDE + wn * 64 + g * 16, BSTRIDE);
            #pragma unroll
            for (int f = 0; f < 2; f++)
                #pragma unroll
                for (int g = 0; g < 4; g++)
                    wmma::mma_sync(acc[f][g], af[f], bf[g], acc[f][g]);
        }
        __syncthreads();
    }

    float* Ep = sm;
    #pragma unroll
    for (int f = 0; f < 2; f++)
        #pragma unroll
        for (int g = 0; g < 4; g++)
            wmma::store_matrix_sync(Ep + (wm * 32 + f * 16) * EPST + wn * 64 + g * 16,
                                    acc[f][g], EPST, wmma::mem_row_major);
    __syncthreads();

    __nv_bfloat16* Vb = V + ((size_t)b * CC + m0) * NN + n0;
    #pragma unroll
    for (int t = tid; t < 128 * 32; t += 256) {
        int r = t >> 5, sc = t & 31;
        float4 a = *(const float4*)(Ep + r * EPST + sc * 4);
        __nv_bfloat162 w0 = __float22bfloat162_rn(make_float2(a.x, a.y));
        __nv_bfloat162 w1 = __float22bfloat162_rn(make_float2(a.z, a.w));
        uint2 u = make_uint2(*(uint32_t*)&w0, *(uint32_t*)&w1);
        *(uint2*)(Vb + (size_t)r * NN + sc * 4) = u;
    }
}

// ===========================================================================
// Fused Q+K projection (tf32 MMA):
//   A rows 0-63 = Wq, rows 64-127 = Wk;  B = x[b][:, n0:n0+128]
//   Q stored transposed [n][o], K stored [o][n].
// ===========================================================================
__global__ void __launch_bounds__(256, 2)
qkproj_kernel(const float* __restrict__ Wq, const float* __restrict__ Wk,
              const float* __restrict__ X,
              float* __restrict__ Q, float* __restrict__ K) {
    extern __shared__ float sm[];

    const int b  = blockIdx.z;
    const int n0 = blockIdx.x * 128;
    const float* Bb = X + (size_t)b * CC * NN + n0;

    const int tid = threadIdx.x;
    const int wid = tid >> 5;
    const int wm = wid >> 1;
    const int wn = wid & 1;

    wmma::fragment<wmma::accumulator, 16, 16, 8, float> acc[2][4];
    #pragma unroll
    for (int f = 0; f < 2; f++)
        #pragma unroll
        for (int g = 0; g < 4; g++)
            wmma::fill_fragment(acc[f][g], 0.0f);

    const uint32_t smb = smem_u32(sm);

    auto issue = [&](int k0, int s) {
        const uint32_t as_u = smb + (uint32_t)(s * NN_STAGE_FLOATS) * 4;
        const uint32_t bs_u = as_u + 128 * ASTRIDE * 4;
        #pragma unroll
        for (int k = 0; k < 4; k++) {
            int t = tid + k * 256;
            int row = t >> 3, seg = t & 7;
            const float* src = (row < 64)
                ? Wq + (size_t)row * CC + k0 + seg * 4
                : Wk + (size_t)(row - 64) * CC + k0 + seg * 4;
            CP_ASYNC16(as_u + (uint32_t)(row * ASTRIDE + seg * 4) * 4, src);
        }
        #pragma unroll
        for (int k = 0; k < 4; k++) {
            int t = tid + k * 256;
            int row = t >> 5, seg = t & 31;
            CP_ASYNC16(bs_u + (uint32_t)(row * BSTRIDE + seg * 4) * 4,
                       Bb + (size_t)(k0 + row) * NN + seg * 4);
        }
        CP_COMMIT();
    };

    issue(0, 0);

    const int nchunks = CC >> 5;   // 16
    for (int c = 0; c < nchunks; c++) {
        const int s = c & 1;
        if (c + 1 < nchunks) { issue((c + 1) << 5, s ^ 1); CP_WAIT(1); }
        else                 { CP_WAIT(0); }
        __syncthreads();

        const float* As = sm + s * NN_STAGE_FLOATS;
        const float* Bs = As + 128 * ASTRIDE;

        #pragma unroll
        for (int kk = 0; kk < 4; kk++) {
            wmma::fragment<wmma::matrix_a, 16, 16, 8, wmma::precision::tf32, wmma::row_major> af[2];
            wmma::fragment<wmma::matrix_b, 16, 16, 8, wmma::precision::tf32, wmma::row_major> bf[4];
            #pragma unroll
            for (int f = 0; f < 2; f++)
                wmma::load_matrix_sync(af[f], As + (wm * 32 + f * 16) * ASTRIDE + kk * 8, ASTRIDE);
            #pragma unroll
            for (int g = 0; g < 4; g++)
                wmma::load_matrix_sync(bf[g], Bs + kk * 8 * BSTRIDE + wn * 64 + g * 16, BSTRIDE);
            #pragma unroll
            for (int f = 0; f < 2; f++)
                #pragma unroll
                for (int g = 0; g < 4; g++)
                    wmma::mma_sync(acc[f][g], af[f], bf[g], acc[f][g]);
        }
        __syncthreads();
    }

    float* Ep = sm;
    #pragma unroll
    for (int f = 0; f < 2; f++)
        #pragma unroll
        for (int g = 0; g < 4; g++)
            wmma::store_matrix_sync(Ep + (wm * 32 + f * 16) * EPST + wn * 64 + g * 16,
                                    acc[f][g], EPST, wmma::mem_row_major);
    __syncthreads();

    // K half (rows 64-127): coalesced fp32 row-major stores
    float* Kb = K + (size_t)b * CQ * NN + n0;
    #pragma unroll
    for (int k = 0; k < 8; k++) {
        int t = tid + k * 256;
        int r = t >> 5, sc = t & 31;      // r in 0..63
        float4 v = *(const float4*)(Ep + (64 + r) * EPST + sc * 4);
        *(float4*)(Kb + (size_t)r * NN + sc * 4) = v;
    }
    // Q half (rows 0-63): transposed stores Q[n][o] (small, 4B scattered)
    float* Qb = Q + (size_t)b * NN * CQ;
    #pragma unroll
    for (int k = 0; k < 4; k++) {
        int t = tid + k * 256;
        int r = t & 63, cg = t >> 6;      // cg in 0..15
        #pragma unroll
        for (int c2 = 0; c2 < 8; c2++) {
            int n = cg * 8 + c2;
            Qb[(size_t)(n0 + n) * CQ + r] = Ep[r * EPST + n];
        }
    }
}

// ===========================================================================
// Energy (tf32 MMA) + exp + row sums, bf16 P output.
// ===========================================================================
__global__ void __launch_bounds__(256, 2)
energy_kernel(const float* __restrict__ Q, const float* __restrict__ K,
              __nv_bfloat16* __restrict__ P, float* __restrict__ l) {
    extern __shared__ float sm[];

    const int b  = blockIdx.z;
    const int i0 = blockIdx.y * 128;
    const int j0b = blockIdx.x * 128;
    const float* Qb = Q + ((size_t)b * NN + i0) * CQ;
    const float* Kb = K + (size_t)b * CQ * NN + j0b;

    const int tid = threadIdx.x;
    const int wid = tid >> 5;
    const int lane = tid & 31;
    const int wm = wid >> 1;
    const int wn = wid & 1;

    wmma::fragment<wmma::accumulator, 16, 16, 8, float> acc[2][4];
    #pragma unroll
    for (int f = 0; f < 2; f++)
        #pragma unroll
        for (int g = 0; g < 4; g++)
            wmma::fill_fragment(acc[f][g], 0.0f);

    const uint32_t smb = smem_u32(sm);

    auto issue = [&](int k0, int s) {
        const uint32_t as_u = smb + (uint32_t)(s * NN_STAGE_FLOATS) * 4;
        const uint32_t bs_u = as_u + 128 * ASTRIDE * 4;
        #pragma unroll
        for (int k = 0; k < 4; k++) {
            int t = tid + k * 256;
            int row = t >> 3, seg = t & 7;
            CP_ASYNC16(as_u + (uint32_t)(row * ASTRIDE + seg * 4) * 4,
                       Qb + (size_t)row * CQ + k0 + seg * 4);
        }
        #pragma unroll
        for (int k = 0; k < 4; k++) {
            int t = tid + k * 256;
            int row = t >> 5, seg = t & 31;
            CP_ASYNC16(bs_u + (uint32_t)(row * BSTRIDE + seg * 4) * 4,
                       Kb + (size_t)(k0 + row) * NN + seg * 4);
        }
        CP_COMMIT();
    };

    issue(0, 0);
    #pragma unroll
    for (int c = 0; c < 2; c++) {
        if (c == 0) { issue(32, 1); CP_WAIT(1); }
        else        { CP_WAIT(0); }
        __syncthreads();

        const float* As = sm + c * NN_STAGE_FLOATS;
        const float* Bs = As + 128 * ASTRIDE;

        #pragma unroll
        for (int kk = 0; kk < 4; kk++) {
            wmma::fragment<wmma::matrix_a, 16, 16, 8, wmma::precision::tf32, wmma::row_major> af[2];
            wmma::fragment<wmma::matrix_b, 16, 16, 8, wmma::precision::tf32, wmma::row_major> bf[4];
            #pragma unroll
            for (int f = 0; f < 2; f++)
                wmma::load_matrix_sync(af[f], As + (wm * 32 + f * 16) * ASTRIDE + kk * 8, ASTRIDE);
            #pragma unroll
            for (int g = 0; g < 4; g++)
                wmma::load_matrix_sync(bf[g], Bs + kk * 8 * BSTRIDE + wn * 64 + g * 16, BSTRIDE);
            #pragma unroll
            for (int f = 0; f < 2; f++)
                #pragma unroll
                for (int g = 0; g < 4; g++)
                    wmma::mma_sync(acc[f][g], af[f], bf[g], acc[f][g]);
        }
        __syncthreads();
    }

    float* Ep = sm;
    #pragma unroll
    for (int f = 0; f < 2; f++)
        #pragma unroll
        for (int g = 0; g < 4; g++) {
            #pragma unroll
            for (int e = 0; e < acc[f][g].num_elements; e++)
                acc[f][g].x[e] = __expf(acc[f][g].x[e]);
            wmma::store_matrix_sync(Ep + (wm * 32 + f * 16) * EPST + wn * 64 + g * 16,
                                    acc[f][g], EPST, wmma::mem_row_major);
        }
    __syncthreads();

    __nv_bfloat16* Pbase = P + (size_t)b * NN * NN + (size_t)i0 * NN + j0b;
    float* lb = l + (size_t)b * NN + i0;
    #pragma unroll
    for (int k = 0; k < 16; k++) {
        const int r = wid + k * 8;
        float4 v = *(const float4*)(Ep + r * EPST + lane * 4);
        __nv_bfloat162 w0 = __float22bfloat162_rn(make_float2(v.x, v.y));
        __nv_bfloat162 w1 = __float22bfloat162_rn(make_float2(v.z, v.w));
        uint2 u = make_uint2(*(uint32_t*)&w0, *(uint32_t*)&w1);
        *(uint2*)(Pbase + (size_t)r * NN + lane * 4) = u;

        float s = (v.x + v.y) + (v.z + v.w);
        #pragma unroll
        for (int o = 16; o > 0; o >>= 1)
            s += __shfl_xor_sync(0xffffffffu, s, o);
        if (lane == 0)
            atomicAdd(lb + r, s);
    }
}

// ===========================================================================
// Out GEMM (bf16 m16n16k16, NT) + fused normalize/gamma/residual.
// Grid: x = c-tiles (2), y = i-tiles (32), z = batch -> c-tile pairs sharing
// a P tile run adjacently (2nd read from L2); V stays L2-resident.
// ===========================================================================
#define OT_M 256
#define OT_N 128
#define KC 64
#define HST 72
#define OT_STAGE_HALVES ((OT_M + OT_N) * HST)            // 27648
#define SMEM_OUT_BYTES  (3 * OT_STAGE_HALVES * 2)        // 165888

__global__ void __launch_bounds__(256, 1)
wmma_out_kernel(const __nv_bfloat16* __restrict__ V,
                const __nv_bfloat16* __restrict__ P,
                const float* __restrict__ x, const float* __restrict__ gamma,
                const float* __restrict__ l, float* __restrict__ out) {
    extern __shared__ float smf[];
    __nv_bfloat16* smh = (__nv_bfloat16*)smf;

    const int b  = blockIdx.z;
    const int c0 = blockIdx.x * OT_M;
    const int i0 = blockIdx.y * OT_N;
    const __nv_bfloat16* Vb = V + ((size_t)b * CC + c0) * NN;
    const __nv_bfloat16* Pb = P + ((size_t)b * NN + i0) * NN;

    const int tid = threadIdx.x;
    const int wid = tid >> 5;
    const int wm = wid >> 1;
    const int wn = wid & 1;

    wmma::fragment<wmma::accumulator, 16, 16, 16, float> acc[4][4];
    #pragma unroll
    for (int f = 0; f < 4; f++)
        #pragma unroll
        for (int g = 0; g < 4; g++)
            wmma::fill_fragment(acc[f][g], 0.0f);

    const uint32_t smb = smem_u32(smh);

    auto issue = [&](int j0, int s) {
        const uint32_t as_u = smb + (uint32_t)(s * OT_STAGE_HALVES) * 2;
        const uint32_t bs_u = as_u + OT_M * HST * 2;
        #pragma unroll
        for (int k = 0; k < 8; k++) {
            int t = tid + k * 256;
            int row = t >> 3, seg = t & 7;
            CP_ASYNC16(as_u + (uint32_t)(row * HST + seg * 8) * 2,
                       Vb + (size_t)row * NN + j0 + seg * 8);
        }
        #pragma unroll
        for (int k = 0; k < 4; k++) {
            int t = tid + k * 256;
            int row = t >> 3, seg = t & 7;
            CP_ASYNC16(bs_u + (uint32_t)(row * HST + seg * 8) * 2,
                       Pb + (size_t)row * NN + j0 + seg * 8);
        }
        CP_COMMIT();
    };

    issue(0, 0);
    issue(KC, 1);

    const int nchunks = NN / KC;   // 64
    for (int c = 0; c < nchunks; c++) {
        if (c + 2 < nchunks) { issue((c + 2) * KC, (c + 2) % 3); CP_WAIT(2); }
        else if (c + 1 < nchunks) { CP_WAIT(1); }
        else { CP_WAIT(0); }
        __syncthreads();

        const __nv_bfloat16* As = smh + (c % 3) * OT_STAGE_HALVES;
        const __nv_bfloat16* Bs = As + OT_M * HST;

        #pragma unroll
        for (int kk = 0; kk < KC / 16; kk++) {
            wmma::fragment<wmma::matrix_a, 16, 16, 16, __nv_bfloat16, wmma::row_major> af[4];
            wmma::fragment<wmma::matrix_b, 16, 16, 16, __nv_bfloat16, wmma::col_major> bf[4];
            #pragma unroll
            for (int f = 0; f < 4; f++)
                wmma::load_matrix_sync(af[f], As + (wm * 64 + f * 16) * HST + kk * 16, HST);
            #pragma unroll
            for (int g = 0; g < 4; g++)
                wmma::load_matrix_sync(bf[g], Bs + (wn * 64 + g * 16) * HST + kk * 16, HST);
            #pragma unroll
            for (int f = 0; f < 4; f++)
                #pragma unroll
                for (int g = 0; g < 4; g++)
                    wmma::mma_sync(acc[f][g], af[f], bf[g], acc[f][g]);
        }
        __syncthreads();
    }

    float* Ep = smf;
    float* linv = smf + OT_M * EPST;
    #pragma unroll
    for (int f = 0; f < 4; f++)
        #pragma unroll
        for (int g = 0; g < 4; g++)
            wmma::store_matrix_sync(Ep + (wm * 64 + f * 16) * EPST + wn * 64 + g * 16,
                                    acc[f][g], EPST, wmma::mem_row_major);
    if (tid < 128)
        linv[tid] = 1.0f / l[(size_t)b * NN + i0 + tid];
    __syncthreads();

    const float gm = gamma[0];
    #pragma unroll
    for (int t = tid; t < OT_M * 32; t += 256) {
        int r = t >> 5, sc = t & 31;
        float4 a = *(const float4*)(Ep + r * EPST + sc * 4);
        size_t gi = ((size_t)b * CC + c0 + r) * NN + i0 + sc * 4;
        float4 xv = *(const float4*)(x + gi);
        float4 o;
        o.x = gm * a.x * linv[sc * 4 + 0] + xv.x;
        o.y = gm * a.y * linv[sc * 4 + 1] + xv.y;
        o.z = gm * a.z * linv[sc * 4 + 2] + xv.z;
        o.w = gm * a.w * linv[sc * 4 + 3] + xv.w;
        *(float4*)(out + gi) = o;
    }
}

// ---------------------------------------------------------------------------
extern "C" void kernel_launch(void* const* d_in, const int* in_sizes, int n_in,
                              void* d_out, int out_size) {
    const float* x     = (const float*)d_in[0];
    const float* Wq    = (const float*)d_in[1];
    const float* Wk    = (const float*)d_in[2];
    const float* Wv    = (const float*)d_in[3];
    const float* gamma = (const float*)d_in[4];
    float* out = (float*)d_out;

    float *Q, *K, *L;
    __nv_bfloat16 *V, *P;
    cudaGetSymbolAddress((void**)&Q, g_Q);
    cudaGetSymbolAddress((void**)&K, g_K);
    cudaGetSymbolAddress((void**)&V, g_V);
    cudaGetSymbolAddress((void**)&P, g_P);
    cudaGetSymbolAddress((void**)&L, g_L);

    cudaFuncSetAttribute(vproj_kernel,
                         cudaFuncAttributeMaxDynamicSharedMemorySize, SMEM_NN_BYTES);
    cudaFuncSetAttribute(qkproj_kernel,
                         cudaFuncAttributeMaxDynamicSharedMemorySize, SMEM_NN_BYTES);
    cudaFuncSetAttribute(energy_kernel,
                         cudaFuncAttributeMaxDynamicSharedMemorySize, SMEM_NN_BYTES);
    cudaFuncSetAttribute(wmma_out_kernel,
                         cudaFuncAttributeMaxDynamicSharedMemorySize, SMEM_OUT_BYTES);

    zero_l_kernel<<<BB * NN / 256, 256>>>(L);

    qkproj_kernel<<<dim3(NN / 128, 1, BB), 256, SMEM_NN_BYTES>>>(Wq, Wk, x, Q, K);

    vproj_kernel<<<dim3(NN / 128, CC / 128, BB), 256, SMEM_NN_BYTES>>>(Wv, x, V);

    energy_kernel<<<dim3(NN / 128, NN / 128, BB), 256, SMEM_NN_BYTES>>>(Q, K, P, L);

    wmma_out_kernel<<<dim3(CC / OT_M, NN / OT_N, BB), 256, SMEM_OUT_BYTES>>>(
        V, P, x, gamma, L, out);
}